// round 1
// baseline (speedup 1.0000x reference)
#include <cuda_runtime.h>
#include <cstddef>

#define D0    128
#define NGRP  64
#define NB    256
#define TTOT  2560

__global__ __launch_bounds__(128)
void ragged_attn_kernel(const float* __restrict__ s_i,
                        const float* __restrict__ theta,
                        float* __restrict__ out)
{
    __shared__ float tile[64 * D0];   // up to 64 tokens x 128 dims
    __shared__ float u_sh[64];
    __shared__ float e_sh[64];
    __shared__ float inv_sh;

    const int bid = blockIdx.x;
    const int b   = bid >> 6;       // batch
    const int g   = bid & 63;       // group

    // sizes cycle 16,32,48,64; starts within a 160-token cycle: 0,16,48,96
    const int gm = g & 3;
    const int nt = (gm + 1) << 4;                       // 16/32/48/64
    const int pre = (gm == 0) ? 0 : (gm == 1) ? 16 : (gm == 2) ? 48 : 96;
    const int t0 = (g >> 2) * 160 + pre;

    const int tid  = threadIdx.x;
    const int lane = tid & 31;
    const int w    = tid >> 5;

    // s_i[b] float4 for this lane's d-chunk (d = 4*lane .. 4*lane+3)
    const float4 sv = __ldg(reinterpret_cast<const float4*>(s_i + (size_t)b * D0) + lane);

    const float4* th4   = reinterpret_cast<const float4*>(theta + ((size_t)b * TTOT + t0) * D0);
    float4*       tile4 = reinterpret_cast<float4*>(tile);

    // ---------- Phase 1: stream tile to SMEM, fused partial dot products ----------
    // Element e = tid + 128*k -> token t = w + 4k, float4-chunk c = lane.
    const int cnt = nt >> 2;        // iterations per warp: 4/8/12/16
    float p[16];

    #pragma unroll
    for (int k = 0; k < 16; k++) {
        if (k < cnt) {
            const int t = w + (k << 2);
            const float4 v = th4[t * 32 + lane];
            tile4[t * 32 + lane] = v;
            p[k] = v.x * sv.x + v.y * sv.y + v.z * sv.z + v.w * sv.w;
        }
    }

    // Per-token warp reduction (partials for token w+4k live across lanes of warp w)
    #pragma unroll
    for (int k = 0; k < 16; k++) {
        if (k < cnt) {
            float r = p[k];
            r += __shfl_xor_sync(0xffffffffu, r, 16);
            r += __shfl_xor_sync(0xffffffffu, r, 8);
            r += __shfl_xor_sync(0xffffffffu, r, 4);
            r += __shfl_xor_sync(0xffffffffu, r, 2);
            r += __shfl_xor_sync(0xffffffffu, r, 1);
            if (lane == 0) u_sh[w + (k << 2)] = r * (1.0f / 128.0f);   // scale by d0
        }
    }
    __syncthreads();

    // ---------- Phase 2: softmax over <=64 scores (warp 0) ----------
    if (tid < 32) {
        const float v0 = (tid      < nt) ? u_sh[tid]      : -3.4e38f;
        const float v1 = (tid + 32 < nt) ? u_sh[tid + 32] : -3.4e38f;
        float m = fmaxf(v0, v1);
        #pragma unroll
        for (int o = 16; o > 0; o >>= 1)
            m = fmaxf(m, __shfl_xor_sync(0xffffffffu, m, o));
        const float e0 = (tid      < nt) ? __expf(v0 - m) : 0.0f;
        const float e1 = (tid + 32 < nt) ? __expf(v1 - m) : 0.0f;
        e_sh[tid]      = e0;
        e_sh[tid + 32] = e1;
        float s = e0 + e1;
        #pragma unroll
        for (int o = 16; o > 0; o >>= 1)
            s += __shfl_xor_sync(0xffffffffu, s, o);
        if (tid == 0) inv_sh = 1.0f / s;
    }
    __syncthreads();

    // ---------- Phase 3: weighted sum, thread-per-d ----------
    float acc0 = 0.0f, acc1 = 0.0f;
    const int d = tid;
    #pragma unroll 4
    for (int t = 0; t < nt; t += 4) {
        acc0 += e_sh[t + 0] * tile[(t + 0) * D0 + d];
        acc1 += e_sh[t + 1] * tile[(t + 1) * D0 + d];
        acc0 += e_sh[t + 2] * tile[(t + 2) * D0 + d];
        acc1 += e_sh[t + 3] * tile[(t + 3) * D0 + d];
    }
    out[((size_t)b * NGRP + g) * D0 + d] = (acc0 + acc1) * inv_sh;
}

extern "C" void kernel_launch(void* const* d_in, const int* in_sizes, int n_in,
                              void* d_out, int out_size)
{
    const float* s_i   = (const float*)d_in[0];   // [256,128]
    const float* theta = (const float*)d_in[1];   // [256,2560,128]
    float* out = (float*)d_out;                   // [256,64,128]
    (void)in_sizes; (void)n_in; (void)out_size;
    ragged_attn_kernel<<<NB * NGRP, 128>>>(s_i, theta, out);
}